// round 7
// baseline (speedup 1.0000x reference)
#include <cuda_runtime.h>
#include <math.h>
#include <stdint.h>

// Problem constants
#define Bsz   4
#define T_LEN 2048
#define E_DIM 1024
#define H_NUM 16
#define D_DIM 64
#define M_TOT (Bsz * T_LEN)   // 8192

// Scratch (allocation-free: device globals)
__device__ float g_q[M_TOT * E_DIM];
__device__ float g_k[M_TOT * E_DIM];
__device__ float g_v[M_TOT * E_DIM];
__device__ float g_att[M_TOT * E_DIM];

// ---------------------------------------------------------------------------
// Shared mma helpers (m16n8k8 tf32, 3-term hi/lo split for fp32 accuracy)
// ---------------------------------------------------------------------------
__device__ __forceinline__ float tf32_round(float x) {
    uint32_t u;
    asm("cvt.rna.tf32.f32 %0, %1;" : "=r"(u) : "f"(x));
    return __uint_as_float(u);
}

__device__ __forceinline__ void split_tf32(float x, uint32_t& hi, uint32_t& lo) {
    float h = tf32_round(x);
    hi = __float_as_uint(h);
    lo = __float_as_uint(tf32_round(x - h));
}

__device__ __forceinline__ void mma_tf32(float* d, const uint32_t* a, const uint32_t* b) {
    asm volatile(
        "mma.sync.aligned.m16n8k8.row.col.f32.tf32.tf32.f32 "
        "{%0,%1,%2,%3},{%4,%5,%6,%7},{%8,%9},{%0,%1,%2,%3};"
        : "+f"(d[0]), "+f"(d[1]), "+f"(d[2]), "+f"(d[3])
        : "r"(a[0]), "r"(a[1]), "r"(a[2]), "r"(a[3]), "r"(b[0]), "r"(b[1]));
}

// acc += A*B with 3-term split (lo*hi + hi*lo + hi*hi)
__device__ __forceinline__ void mma_split3(float* acc, const uint32_t* ahi, const uint32_t* alo,
                                           const uint32_t* bhi, const uint32_t* blo) {
    mma_tf32(acc, alo, bhi);
    mma_tf32(acc, ahi, blo);
    mma_tf32(acc, ahi, bhi);
}

// ---------------------------------------------------------------------------
// Tensor-core GEMM (3xTF32 split): C[M,N] = A[M,K] @ W[N,K]^T + bias[N]
// CTA tile 128x64x16, 256 threads = 8 warps (4 m x 2 n), warp tile 32x32.
// ---------------------------------------------------------------------------
#define BM  128
#define BN  64
#define BK  16
#define BKP 17   // pad to limit smem bank conflicts on fragment gathers

__device__ __forceinline__
void gemm_bias_body(const float* __restrict__ A, const float* __restrict__ W,
                    const float* __restrict__ bias, float* __restrict__ C,
                    int m0, int n0)
{
    __shared__ float As[2][BM][BKP];   // [row m][k]
    __shared__ float Ws[2][BN][BKP];   // [row n][k]

    const int tid  = threadIdx.x;
    const int lane = tid & 31;
    const int wid  = tid >> 5;
    const int g    = lane >> 2;        // groupID (0..7)
    const int c    = lane & 3;         // threadID_in_group (0..3)
    const int warp_m = wid & 3;        // 0..3
    const int warp_n = wid >> 2;       // 0..1
    const int m_off = warp_m * 32;
    const int n_off = warp_n * 32;

    const int lr = tid >> 2;           // 0..63 (A rows lr, lr+64)
    const int lc = tid & 3;            // float4 index in the 16-wide K slab

    const float* Abase  = A + (size_t)(m0 + lr) * E_DIM + lc * 4;
    const float* A2base = Abase + (size_t)64 * E_DIM;
    const float* Wbase  = W + (size_t)(n0 + lr) * E_DIM + lc * 4;

    float acc[2][4][4];
#pragma unroll
    for (int mt = 0; mt < 2; mt++)
#pragma unroll
        for (int nt = 0; nt < 4; nt++)
#pragma unroll
            for (int q = 0; q < 4; q++) acc[mt][nt][q] = 0.f;

    // Preload first K slab into buffer 0
    {
        float4 va0 = *(const float4*)(Abase);
        float4 va1 = *(const float4*)(A2base);
        float4 vw  = *(const float4*)(Wbase);
#pragma unroll
        for (int j = 0; j < 4; j++) {
            As[0][lr][lc * 4 + j]      = ((const float*)&va0)[j];
            As[0][lr + 64][lc * 4 + j] = ((const float*)&va1)[j];
            Ws[0][lr][lc * 4 + j]      = ((const float*)&vw)[j];
        }
    }
    __syncthreads();

    int buf = 0;
    for (int k0 = BK; k0 <= E_DIM; k0 += BK) {
        float4 pa0, pa1, pw;
        const bool more = (k0 < E_DIM);
        if (more) {
            pa0 = *(const float4*)(Abase + k0);
            pa1 = *(const float4*)(A2base + k0);
            pw  = *(const float4*)(Wbase + k0);
        }

#pragma unroll
        for (int ks = 0; ks < 2; ks++) {
            const int kb = ks * 8;

            uint32_t bhi[4][2], blo[4][2];
#pragma unroll
            for (int nt = 0; nt < 4; nt++) {
                const int nrow = n_off + nt * 8 + g;
                split_tf32(Ws[buf][nrow][kb + c],     bhi[nt][0], blo[nt][0]);
                split_tf32(Ws[buf][nrow][kb + c + 4], bhi[nt][1], blo[nt][1]);
            }

#pragma unroll
            for (int mt = 0; mt < 2; mt++) {
                const int mb = m_off + mt * 16;
                uint32_t ahi[4], alo[4];
                split_tf32(As[buf][mb + g][kb + c],         ahi[0], alo[0]);
                split_tf32(As[buf][mb + g + 8][kb + c],     ahi[1], alo[1]);
                split_tf32(As[buf][mb + g][kb + c + 4],     ahi[2], alo[2]);
                split_tf32(As[buf][mb + g + 8][kb + c + 4], ahi[3], alo[3]);

#pragma unroll
                for (int nt = 0; nt < 4; nt++)
                    mma_split3(acc[mt][nt], ahi, alo, bhi[nt], blo[nt]);
            }
        }

        if (more) {
            const int nbuf = buf ^ 1;
#pragma unroll
            for (int j = 0; j < 4; j++) {
                As[nbuf][lr][lc * 4 + j]      = ((const float*)&pa0)[j];
                As[nbuf][lr + 64][lc * 4 + j] = ((const float*)&pa1)[j];
                Ws[nbuf][lr][lc * 4 + j]      = ((const float*)&pw)[j];
            }
            __syncthreads();
            buf = nbuf;
        }
    }

    // Epilogue: bias + store
#pragma unroll
    for (int nt = 0; nt < 4; nt++) {
        const int col = n0 + n_off + nt * 8 + 2 * c;
        const float2 bb = *(const float2*)(bias + col);
#pragma unroll
        for (int mt = 0; mt < 2; mt++) {
            const int r0 = m0 + m_off + mt * 16 + g;
            float2 v0, v1;
            v0.x = acc[mt][nt][0] + bb.x; v0.y = acc[mt][nt][1] + bb.y;
            v1.x = acc[mt][nt][2] + bb.x; v1.y = acc[mt][nt][3] + bb.y;
            *(float2*)(C + (size_t)r0 * E_DIM + col)       = v0;
            *(float2*)(C + (size_t)(r0 + 8) * E_DIM + col) = v1;
        }
    }
}

__global__ __launch_bounds__(256, 2)
void qkv_gemm_kernel(const float* __restrict__ x,
                     const float* __restrict__ Wq, const float* __restrict__ bq,
                     const float* __restrict__ Wk, const float* __restrict__ bk,
                     const float* __restrict__ Wv, const float* __restrict__ bv,
                     float* __restrict__ q, float* __restrict__ k, float* __restrict__ v)
{
    const int which = blockIdx.z;
    const float* W = (which == 0) ? Wq : (which == 1) ? Wk : Wv;
    const float* b = (which == 0) ? bq : (which == 1) ? bk : bv;
    float*       C = (which == 0) ? q  : (which == 1) ? k  : v;
    gemm_bias_body(x, W, b, C, blockIdx.y * BM, blockIdx.x * BN);
}

__global__ __launch_bounds__(256, 2)
void out_gemm_kernel(const float* __restrict__ A, const float* __restrict__ W,
                     const float* __restrict__ bias, float* __restrict__ C)
{
    gemm_bias_body(A, W, bias, C, blockIdx.y * BM, blockIdx.x * BN);
}

// ---------------------------------------------------------------------------
// Tensor-core flash attention.
// CTA: 128 threads = 4 warps; 64-query tile; warp w owns rows w*16..w*16+15.
// K and V both kept natural [key][d]: K is the B operand of S = Q@K^T and
// natural V is directly the B operand of O += P@V (B[k][n] = V[key][d]).
// P round-trips through per-warp smem rows. All matmuls: 3xTF32 split.
// K/V tiles prefetched global->registers while previous tile computes.
// Smem stride 68 floats.
// ---------------------------------------------------------------------------
#define ATTN_SCALE 0.125f   // 1/sqrt(64)
#define AST 68              // smem row stride (floats)

__global__ __launch_bounds__(128)
void attn_kernel()
{
    extern __shared__ float smem[];
    float* Ks = smem;               // [key][d]   64 x AST
    float* Vs = Ks + 64 * AST;      // [key][d]   64 x AST
    float* Ps = Vs + 64 * AST;      // [q][key]   64 x AST

    const int tid  = threadIdx.x;
    const int lane = tid & 31;
    const int w    = tid >> 5;      // warp 0..3
    const int g    = lane >> 2;     // 0..7
    const int c    = lane & 3;      // 0..3

    const int qt = blockIdx.x;      // query tile (0..31)
    const int h  = blockIdx.y;
    const int b  = blockIdx.z;

    const size_t rowbase = (size_t)b * T_LEN;
    const int hcol = h * D_DIM;

    const int qrow0 = qt * 64 + w * 16 + g;      // global q row (this thread, half 0)
    const int qrow1 = qrow0 + 8;

    // Load Q fragments once (scaled): qf[kstep][0..3]
    float qf[8][4];
#pragma unroll
    for (int kb = 0; kb < 8; kb++) {
        const int col0 = hcol + kb * 8 + c;
        qf[kb][0] = g_q[(rowbase + qrow0) * E_DIM + col0]     * ATTN_SCALE;
        qf[kb][1] = g_q[(rowbase + qrow1) * E_DIM + col0]     * ATTN_SCALE;
        qf[kb][2] = g_q[(rowbase + qrow0) * E_DIM + col0 + 4] * ATTN_SCALE;
        qf[kb][3] = g_q[(rowbase + qrow1) * E_DIM + col0 + 4] * ATTN_SCALE;
    }

    // Per-thread global-load slots: 8 rows x 1 float4, for K and V
    const int ld_row = tid >> 4;            // 0..7 base row
    const int ld_f4  = tid & 15;            // float4 column 0..15

    float o[8][4];                  // O accumulator: 8 d-tiles of m16n8
#pragma unroll
    for (int nt = 0; nt < 8; nt++)
#pragma unroll
        for (int q = 0; q < 4; q++) o[nt][q] = 0.f;
    float mrow[2] = {-1e30f, -1e30f};
    float lrow[2] = {0.f, 0.f};

    // Prefetch first K/V tile into registers
    float4 pk[8], pv[8];
#pragma unroll
    for (int it = 0; it < 8; it++) {
        const int row = ld_row + it * 8;
        const size_t grow = (rowbase + row) * E_DIM + hcol + ld_f4 * 4;
        pk[it] = *(const float4*)(g_k + grow);
        pv[it] = *(const float4*)(g_v + grow);
    }

    for (int kt = 0; kt < T_LEN / 64; kt++) {
        __syncthreads();            // all warps done reading Ks/Vs from prev iter
        // Commit prefetched tile to smem (both natural [key][d], float4 STS)
#pragma unroll
        for (int it = 0; it < 8; it++) {
            const int row = ld_row + it * 8;
            *(float4*)&Ks[row * AST + ld_f4 * 4] = pk[it];
            *(float4*)&Vs[row * AST + ld_f4 * 4] = pv[it];
        }
        __syncthreads();

        // Prefetch next tile (overlaps with compute below)
        if (kt + 1 < T_LEN / 64) {
#pragma unroll
            for (int it = 0; it < 8; it++) {
                const int row = (kt + 1) * 64 + ld_row + it * 8;
                const size_t grow = (rowbase + row) * E_DIM + hcol + ld_f4 * 4;
                pk[it] = *(const float4*)(g_k + grow);
                pv[it] = *(const float4*)(g_v + grow);
            }
        }

        // S = Q @ K^T : s[nt] covers keys nt*8..nt*8+7
        float s[8][4];
#pragma unroll
        for (int nt = 0; nt < 8; nt++)
#pragma unroll
            for (int q = 0; q < 4; q++) s[nt][q] = 0.f;

#pragma unroll
        for (int kb = 0; kb < 8; kb++) {
            uint32_t ahi[4], alo[4];
#pragma unroll
            for (int q = 0; q < 4; q++) split_tf32(qf[kb][q], ahi[q], alo[q]);
#pragma unroll
            for (int nt = 0; nt < 8; nt++) {
                uint32_t bhi[2], blo[2];
                split_tf32(Ks[(nt * 8 + g) * AST + kb * 8 + c],     bhi[0], blo[0]);
                split_tf32(Ks[(nt * 8 + g) * AST + kb * 8 + c + 4], bhi[1], blo[1]);
                mma_split3(s[nt], ahi, alo, bhi, blo);
            }
        }

        // Online softmax per row half (ri=0: row g; ri=1: row g+8)
#pragma unroll
        for (int ri = 0; ri < 2; ri++) {
            float mx = -1e30f;
#pragma unroll
            for (int nt = 0; nt < 8; nt++)
                mx = fmaxf(mx, fmaxf(s[nt][2 * ri], s[nt][2 * ri + 1]));
            mx = fmaxf(mx, __shfl_xor_sync(0xffffffffu, mx, 1));
            mx = fmaxf(mx, __shfl_xor_sync(0xffffffffu, mx, 2));
            const float mnew  = fmaxf(mrow[ri], mx);
            const float alpha = __expf(mrow[ri] - mnew);
            float rs = 0.f;
#pragma unroll
            for (int nt = 0; nt < 8; nt++) {
                s[nt][2 * ri]     = __expf(s[nt][2 * ri] - mnew);
                s[nt][2 * ri + 1] = __expf(s[nt][2 * ri + 1] - mnew);
                rs += s[nt][2 * ri] + s[nt][2 * ri + 1];
            }
            rs += __shfl_xor_sync(0xffffffffu, rs, 1);
            rs += __shfl_xor_sync(0xffffffffu, rs, 2);
            lrow[ri] = lrow[ri] * alpha + rs;
            mrow[ri] = mnew;
#pragma unroll
            for (int nt = 0; nt < 8; nt++) {
                o[nt][2 * ri]     *= alpha;
                o[nt][2 * ri + 1] *= alpha;
            }
        }

        // Write P to this warp's smem rows, then read back as A fragments
        {
            const int pr0 = w * 16 + g;
#pragma unroll
            for (int nt = 0; nt < 8; nt++) {
                *(float2*)&Ps[pr0 * AST + nt * 8 + 2 * c]       = make_float2(s[nt][0], s[nt][1]);
                *(float2*)&Ps[(pr0 + 8) * AST + nt * 8 + 2 * c] = make_float2(s[nt][2], s[nt][3]);
            }
        }
        __syncwarp();

        // O += P @ V : B operand read directly from natural Vs[key][d]
#pragma unroll
        for (int kb = 0; kb < 8; kb++) {
            const int pr0 = w * 16 + g;
            uint32_t phi[4], plo[4];
            split_tf32(Ps[pr0 * AST + kb * 8 + c],           phi[0], plo[0]);
            split_tf32(Ps[(pr0 + 8) * AST + kb * 8 + c],     phi[1], plo[1]);
            split_tf32(Ps[pr0 * AST + kb * 8 + c + 4],       phi[2], plo[2]);
            split_tf32(Ps[(pr0 + 8) * AST + kb * 8 + c + 4], phi[3], plo[3]);
#pragma unroll
            for (int nt = 0; nt < 8; nt++) {
                uint32_t bhi[2], blo[2];
                split_tf32(Vs[(kb * 8 + c) * AST + nt * 8 + g],       bhi[0], blo[0]);
                split_tf32(Vs[(kb * 8 + c + 4) * AST + nt * 8 + g],   bhi[1], blo[1]);
                mma_split3(o[nt], phi, plo, bhi, blo);
            }
        }
        __syncwarp();   // Ps reads done before next iteration overwrites
    }

    // Normalize and write out
    const float inv0 = 1.f / lrow[0];
    const float inv1 = 1.f / lrow[1];
#pragma unroll
    for (int nt = 0; nt < 8; nt++) {
        const int col = hcol + nt * 8 + 2 * c;
        *(float2*)(g_att + (rowbase + qrow0) * E_DIM + col) =
            make_float2(o[nt][0] * inv0, o[nt][1] * inv0);
        *(float2*)(g_att + (rowbase + qrow1) * E_DIM + col) =
            make_float2(o[nt][2] * inv1, o[nt][3] * inv1);
    }
}

// ---------------------------------------------------------------------------
extern "C" void kernel_launch(void* const* d_in, const int* in_sizes, int n_in,
                              void* d_out, int out_size)
{
    const float* x  = (const float*)d_in[0];
    const float* Wq = (const float*)d_in[1];
    const float* bq = (const float*)d_in[2];
    const float* Wk = (const float*)d_in[3];
    const float* bk = (const float*)d_in[4];
    const float* Wv = (const float*)d_in[5];
    const float* bv = (const float*)d_in[6];
    const float* Wo = (const float*)d_in[7];
    const float* bo = (const float*)d_in[8];

    float *qp, *kp, *vp, *ap;
    cudaGetSymbolAddress((void**)&qp, g_q);
    cudaGetSymbolAddress((void**)&kp, g_k);
    cudaGetSymbolAddress((void**)&vp, g_v);
    cudaGetSymbolAddress((void**)&ap, g_att);

    // Fused Q/K/V projections: one launch, z selects the projection.
    qkv_gemm_kernel<<<dim3(E_DIM / BN, M_TOT / BM, 3), 256>>>(
        x, Wq, bq, Wk, bk, Wv, bv, qp, kp, vp);

    const int attn_smem = 3 * 64 * AST * sizeof(float);   // 52224 B
    cudaFuncSetAttribute(attn_kernel, cudaFuncAttributeMaxDynamicSharedMemorySize, attn_smem);
    attn_kernel<<<dim3(T_LEN / 64, H_NUM, Bsz), 128, attn_smem>>>();

    out_gemm_kernel<<<dim3(E_DIM / BN, M_TOT / BM), 256>>>(ap, Wo, bo, (float*)d_out);
}